// round 11
// baseline (speedup 1.0000x reference)
#include <cuda_runtime.h>
#include <cstdint>

#define N_NODES 13
#define N_REAL  12
#define BB      4
#define CC      3
#define HH      256
#define WW      256
#define EE      37
#define HWSZ    (HH*WW)

// Packed activation row: 132 float2. idx 0 = {0, a[127]}, idx 1+j = {a[j], a[j+128]}
// (j=0..127), idx 129 = {a[128],0}, idx 130 = {a[129],0}, idx 131 = pad.
#define PROW 132
#define NROWS_TOTAL (N_NODES*BB*CC*HH)
#define TROWS 11
#define PLANE_F2 (TROWS*PROW)          // 1452 float2 per ci-plane tile
#define PLANE_BYTES (PLANE_F2*8)       // 11616 B
#define NSLOT 4
#define DYN_BYTES (NSLOT*PLANE_BYTES)  // 46464 B dynamic smem
#define NTILES 1536                    // 12 v * 4 b * 32 stripes
#define NCTA 592                       // 4 CTAs/SM * 148 SMs
typedef unsigned long long ull;

__device__ float2 g_pk[NROWS_TOTAL*PROW];    // packed sigmoid activations (~42 MB)
__device__ float2 g_wpk[EE*144];             // duplicated {w,w} weight pairs
__device__ int    g_deg[N_REAL];
__device__ int    g_esr[N_REAL][4];
__device__ int    g_eid[N_REAL][4];
__device__ float  g_bsum[N_REAL][3];
__device__ unsigned g_ctr;                   // tile work-steal counter

__device__ __forceinline__ void upk2(ull v, float& lo, float& hi){
  asm("mov.b64 {%0, %1}, %2;" : "=f"(lo), "=f"(hi) : "l"(v));
}
__device__ __forceinline__ ull ffma2(ull a, ull b, ull c){
  ull d; asm("fma.rn.f32x2 %0, %1, %2, %3;" : "=l"(d) : "l"(a), "l"(b), "l"(c));
  return d;
}
__device__ __forceinline__ void cp16(uint32_t s, const void* g){
  asm volatile("cp.async.cg.shared.global [%0], [%1], 16;" :: "r"(s), "l"(g));
}
__device__ __forceinline__ float sigf(float x){
  return __fdividef(1.f, 1.f + __expf(-x));
}

// ---------- pass 1: setup (block 0) + sigmoid pack + halo (blocks 1..) ----------
__global__ void sigmoid_pack_all(const float* __restrict__ x,
                                 const float* __restrict__ Wt,
                                 const float* __restrict__ Bs,
                                 const int*   __restrict__ esrc,
                                 const int*   __restrict__ edst){
  if (blockIdx.x == 0){
    int t = threadIdx.x;
    for (int i=t; i<EE*144; i+=256){ float w=__ldg(&Wt[i]); g_wpk[i]=make_float2(w,w); }
    if (t < N_REAL){
      int d=0; float b0=0.f,b1=0.f,b2=0.f;
      for (int e=0; e<EE; e++)
        if (__ldg(&edst[e]) == t){
          g_esr[t][d]=__ldg(&esrc[e]); g_eid[t][d]=e;
          b0+=__ldg(&Bs[e*3+0]); b1+=__ldg(&Bs[e*3+1]); b2+=__ldg(&Bs[e*3+2]);
          d++;
        }
      g_deg[t]=d; g_bsum[t][0]=b0; g_bsum[t][1]=b1; g_bsum[t][2]=b2;
    }
    if (t == 0) g_ctr = 0u;
    return;
  }
  int idx = (blockIdx.x-1)*256 + threadIdx.x;     // 0 .. NROWS_TOTAL*32-1
  int rid = idx >> 5, q = idx & 31;
  const float4* in4 = (const float4*)(x + (size_t)rid*WW);
  float4 lo = __ldg(in4 + q);
  float4 hi = __ldg(in4 + q + 32);
  float slx=sigf(lo.x), sly=sigf(lo.y), slz=sigf(lo.z), slw=sigf(lo.w);
  float shx=sigf(hi.x), shy=sigf(hi.y), shz=sigf(hi.z), shw=sigf(hi.w);
  float2* row = g_pk + (size_t)rid*PROW;
  float2* o = row + 1 + 4*q;
  o[0] = make_float2(slx, shx);
  o[1] = make_float2(sly, shy);
  o[2] = make_float2(slz, shz);
  o[3] = make_float2(slw, shw);
  if (q == 31) row[0]   = make_float2(0.f, slw);    // {0, s(a127)}
  if (q == 0){
    row[129] = make_float2(shx, 0.f);               // {s(a128), 0}
    row[130] = make_float2(shy, 0.f);               // {s(a129), 0}
    row[131] = make_float2(0.f, 0.f);
  }
}

// ---------- conv compute helpers ----------
__device__ __forceinline__ void load8(ull (&R)[8], const ull* rows, int rowidx, int base0){
  const ull* rp = rows + rowidx*PROW;
  #pragma unroll
  for (int mm=0; mm<2; mm++)
    #pragma unroll
    for (int k=0; k<4; k++) R[mm*4+k] = rp[base0 + 32*mm + k];
}
// T = input rows for out row rl=0, Bt = rows for rl=1 (this ky).
__device__ __forceinline__ void fma_ky(ull (&acc)[3][2][4],
                                       const ull (&T)[8], const ull (&Bt)[8],
                                       const float2* wb, int ci, int ky, int mh){
  #pragma unroll
  for (int co=0; co<3; co++){
    const ulonglong2* wp = (const ulonglong2*)(wb + (co*3+ci)*16 + ky*4);
    ulonglong2 w01 = wp[0], w23 = wp[1];    // broadcast LDS.128
    #pragma unroll
    for (int mm=0; mm<2; mm++){
      const int m = 2*mh + mm;
      acc[co][0][m] = ffma2(T[mm*4+0],  w01.x, acc[co][0][m]);
      acc[co][0][m] = ffma2(T[mm*4+1],  w01.y, acc[co][0][m]);
      acc[co][0][m] = ffma2(T[mm*4+2],  w23.x, acc[co][0][m]);
      acc[co][0][m] = ffma2(T[mm*4+3],  w23.y, acc[co][0][m]);
      acc[co][1][m] = ffma2(Bt[mm*4+0], w01.x, acc[co][1][m]);
      acc[co][1][m] = ffma2(Bt[mm*4+1], w01.y, acc[co][1][m]);
      acc[co][1][m] = ffma2(Bt[mm*4+2], w23.x, acc[co][1][m]);
      acc[co][1][m] = ffma2(Bt[mm*4+3], w23.y, acc[co][1][m]);
    }
  }
}

// ---------- pass 2: persistent conv + segment mean ----------
extern __shared__ __align__(16) float2 dynslot[];

__global__ void __launch_bounds__(128, 4) conv_kernel(float* __restrict__ out){
  __shared__ __align__(16) float2 w_all[4*144];
  __shared__ unsigned s_tile;

  const int tx  = threadIdx.x;
  const int ty  = threadIdx.y;
  const int tid = ty*32 + tx;
  const int r0  = 2*ty;

  const uint32_t slot_u32 = (uint32_t)__cvta_generic_to_shared(&dynslot[0]);
  const uint32_t wall_u32 = (uint32_t)__cvta_generic_to_shared(&w_all[0]);

  int prev_v = -1, deg = 0;
  int src[4] = {0,0,0,0}, eid[4] = {0,0,0,0};
  float bsum[3] = {0.f,0.f,0.f};

  for (;;){
    if (tid == 0) s_tile = atomicAdd(&g_ctr, 1u);
    __syncthreads();                       // tile start: also fences slot/w_all reuse
    const unsigned t = s_tile;
    if (t >= NTILES) break;
    const int v   = (int)(t >> 7);
    const int rem = (int)(t & 127u);
    const int b   = rem >> 5;
    const int y0  = (rem & 31) * 8;
    const bool vch = (v != prev_v);
    if (vch){
      prev_v = v;
      deg = g_deg[v];
      #pragma unroll
      for (int i=0; i<4; i++){ src[i] = g_esr[v][i]; eid[i] = g_eid[v][i]; }
      bsum[0]=g_bsum[v][0]; bsum[1]=g_bsum[v][1]; bsum[2]=g_bsum[v][2];
    }

    // Fill one ci-plane into slot si.
    auto fill = [&](int si, int node, int ci){
      const float2* gplane = g_pk + ((((size_t)node*BB + b)*CC + ci)*HH)*(size_t)PROW;
      uint32_t sb = slot_u32 + (uint32_t)(si*PLANE_BYTES);
      for (int w = tid; w < TROWS*66; w += 128){
        int rr = w / 66;
        int c  = w - rr*66;
        int gy = y0 + rr - 1;
        uint32_t off = (uint32_t)(rr*(PROW*8) + c*16);
        if ((unsigned)gy < (unsigned)HH)
          cp16(sb + off, (const char*)(gplane + (size_t)gy*PROW) + c*16);
        else
          asm volatile("st.shared.v4.b32 [%0], {%1,%1,%1,%1};"
                       :: "r"(sb + off), "r"(0) : "memory");
      }
    };

    // Prologue: (weights if v changed) + planes 0..2 as 3 groups.
    if (vch){
      for (int q = tid; q < deg*72; q += 128){
        int e = q/72, c = q - e*72;
        cp16(wall_u32 + (uint32_t)((e*72 + c)*16),
             (const char*)(g_wpk + eid[e]*144) + c*16);
      }
    }
    fill(0, src[0], 0);
    asm volatile("cp.async.commit_group;" ::: "memory");
    fill(1, src[0], 1);
    asm volatile("cp.async.commit_group;" ::: "memory");
    fill(2, src[0], 2);
    asm volatile("cp.async.commit_group;" ::: "memory");

    ull acc[3][2][4];
    #pragma unroll
    for (int co=0; co<3; co++)
      #pragma unroll
      for (int rl=0; rl<2; rl++)
        #pragma unroll
        for (int m=0; m<4; m++) acc[co][rl][m] = 0ull;

    const int S = 3*deg;
    for (int s=0; s<S; s++){
      asm volatile("cp.async.wait_group 2;" ::: "memory");
      __syncthreads();                  // publish plane s
      if (s+3 < S){
        int s3 = s+3, i3 = s3/3;
        fill(s3 & (NSLOT-1), src[i3], s3 - 3*i3);
      }
      asm volatile("cp.async.commit_group;" ::: "memory");

      const int i  = s/3;
      const int ci = s - 3*i;
      const ull* rows  = (const ull*)&dynslot[(s & (NSLOT-1))*PLANE_F2];
      const float2* wb = w_all + i*144;

      #pragma unroll
      for (int mh=0; mh<2; mh++){
        const int base0 = tx + 64*mh;
        ull Ra[8], Rb[8];
        load8(Ra, rows, r0,   base0);
        load8(Rb, rows, r0+1, base0); fma_ky(acc, Ra, Rb, wb, ci, 0, mh);
        load8(Ra, rows, r0+2, base0); fma_ky(acc, Rb, Ra, wb, ci, 1, mh);
        load8(Rb, rows, r0+3, base0); fma_ky(acc, Ra, Rb, wb, ci, 2, mh);
        load8(Ra, rows, r0+4, base0); fma_ky(acc, Rb, Ra, wb, ci, 3, mh);
      }
    }

    // Epilogue: bias + mean, store both columns of each pair.
    const float inv = 1.f / (float)deg;
    #pragma unroll
    for (int co=0; co<3; co++){
      #pragma unroll
      for (int rl=0; rl<2; rl++){
        float* ob = out + (((size_t)v*BB + b)*CC + co)*HWSZ + (y0 + r0 + rl)*WW;
        #pragma unroll
        for (int m=0; m<4; m++){
          float lo, hi;
          upk2(acc[co][rl][m], lo, hi);
          int x = tx + 32*m;
          ob[x]       = (lo + bsum[co]) * inv;
          ob[x + 128] = (hi + bsum[co]) * inv;
        }
      }
    }
  }
}

extern "C" void kernel_launch(void* const* d_in, const int* in_sizes, int n_in,
                              void* d_out, int out_size){
  const float* states  = (const float*)d_in[0];
  const float* weights = (const float*)d_in[1];
  const float* bias    = (const float*)d_in[2];
  const int*   esrc    = (const int*)d_in[3];
  const int*   edst    = (const int*)d_in[4];
  float*       out     = (float*)d_out;

  const int nmain_blocks = (NROWS_TOTAL*32)/256;     // 4992
  sigmoid_pack_all<<<nmain_blocks + 1, 256>>>(states, weights, bias, esrc, edst);

  static int smem_set = 0;
  if (!smem_set){
    cudaFuncSetAttribute(conv_kernel, cudaFuncAttributeMaxDynamicSharedMemorySize,
                         DYN_BYTES);
    smem_set = 1;
  }
  conv_kernel<<<NCTA, dim3(32,4), DYN_BYTES>>>(out);
}

// round 12
// speedup vs baseline: 1.1056x; 1.1056x over previous
#include <cuda_runtime.h>
#include <cstdint>

#define N_NODES 13
#define N_REAL  12
#define BB      4
#define CC      3
#define HH      256
#define WW      256
#define EE      37
#define HWSZ    (HH*WW)

// Packed activation row: 132 float2. idx 0 = {0, a[127]}, idx 1+j = {a[j], a[j+128]}
// (j=0..127), idx 129 = {a[128],0}, idx 130 = {a[129],0}, idx 131 = pad.
#define PROW 132
#define ROWB (PROW*8)                  // 1056 B per packed row (16B multiple)
#define NROWS_TOTAL (N_NODES*BB*CC*HH)
#define TROWS 11
#define PLANE_F2 (TROWS*PROW)          // 1452 float2 per ci-plane tile
#define PLANE_BYTES (PLANE_F2*8)       // 11616 B
#define NSLOT 4
#define DYN_BYTES (NSLOT*PLANE_BYTES)  // 46464 B dynamic smem
#define NTILES 1536                    // 12 v * 4 b * 32 stripes
#define NCTA 592
typedef unsigned long long ull;

__device__ __align__(16) float2 g_pk[NROWS_TOTAL*PROW];
__device__ float2 g_wpk[EE*144];
__device__ int    g_deg[N_REAL];
__device__ int    g_esr[N_REAL][4];
__device__ int    g_eid[N_REAL][4];
__device__ float  g_bsum[N_REAL][3];
__device__ unsigned g_ctr;

__device__ __forceinline__ void upk2(ull v, float& lo, float& hi){
  asm("mov.b64 {%0, %1}, %2;" : "=f"(lo), "=f"(hi) : "l"(v));
}
__device__ __forceinline__ ull ffma2(ull a, ull b, ull c){
  ull d; asm("fma.rn.f32x2 %0, %1, %2, %3;" : "=l"(d) : "l"(a), "l"(b), "l"(c));
  return d;
}
__device__ __forceinline__ float sigf(float x){
  return __fdividef(1.f, 1.f + __expf(-x));
}
__device__ __forceinline__ void mbar_init(uint32_t bar){
  asm volatile("mbarrier.init.shared.b64 [%0], 1;" :: "r"(bar) : "memory");
}
__device__ __forceinline__ void mbar_expect_tx(uint32_t bar, uint32_t n){
  asm volatile("mbarrier.arrive.expect_tx.shared.b64 _, [%0], %1;"
               :: "r"(bar), "r"(n) : "memory");
}
__device__ __forceinline__ void tma_bulk(uint32_t dst, const void* src,
                                         uint32_t n, uint32_t bar){
  asm volatile("cp.async.bulk.shared::cta.global.mbarrier::complete_tx::bytes "
               "[%0], [%1], %2, [%3];"
               :: "r"(dst), "l"(src), "r"(n), "r"(bar) : "memory");
}
__device__ __forceinline__ void mbar_wait(uint32_t bar, uint32_t parity){
  asm volatile(
      "{\n\t.reg .pred P;\n\t"
      "WAIT_%=:\n\t"
      "mbarrier.try_wait.parity.acquire.cta.shared::cta.b64 P, [%0], %1, 0x989680;\n\t"
      "@P bra.uni DONE_%=;\n\t"
      "bra.uni WAIT_%=;\n\t"
      "DONE_%=:\n\t}"
      :: "r"(bar), "r"(parity) : "memory");
}

// ---------- pass 1: setup (block 0) + sigmoid pack + halo (blocks 1..) ----------
__global__ void sigmoid_pack_all(const float* __restrict__ x,
                                 const float* __restrict__ Wt,
                                 const float* __restrict__ Bs,
                                 const int*   __restrict__ esrc,
                                 const int*   __restrict__ edst){
  if (blockIdx.x == 0){
    int t = threadIdx.x;
    for (int i=t; i<EE*144; i+=256){ float w=__ldg(&Wt[i]); g_wpk[i]=make_float2(w,w); }
    if (t < N_REAL){
      int d=0; float b0=0.f,b1=0.f,b2=0.f;
      for (int e=0; e<EE; e++)
        if (__ldg(&edst[e]) == t){
          g_esr[t][d]=__ldg(&esrc[e]); g_eid[t][d]=e;
          b0+=__ldg(&Bs[e*3+0]); b1+=__ldg(&Bs[e*3+1]); b2+=__ldg(&Bs[e*3+2]);
          d++;
        }
      g_deg[t]=d; g_bsum[t][0]=b0; g_bsum[t][1]=b1; g_bsum[t][2]=b2;
    }
    if (t == 0) g_ctr = 0u;
    return;
  }
  int idx = (blockIdx.x-1)*256 + threadIdx.x;
  int rid = idx >> 5, q = idx & 31;
  const float4* in4 = (const float4*)(x + (size_t)rid*WW);
  float4 lo = __ldg(in4 + q);
  float4 hi = __ldg(in4 + q + 32);
  float slx=sigf(lo.x), sly=sigf(lo.y), slz=sigf(lo.z), slw=sigf(lo.w);
  float shx=sigf(hi.x), shy=sigf(hi.y), shz=sigf(hi.z), shw=sigf(hi.w);
  float2* row = g_pk + (size_t)rid*PROW;
  float2* o = row + 1 + 4*q;
  o[0] = make_float2(slx, shx);
  o[1] = make_float2(sly, shy);
  o[2] = make_float2(slz, shz);
  o[3] = make_float2(slw, shw);
  if (q == 31) row[0]   = make_float2(0.f, slw);
  if (q == 0){
    row[129] = make_float2(shx, 0.f);
    row[130] = make_float2(shy, 0.f);
    row[131] = make_float2(0.f, 0.f);
  }
}

// ---------- conv compute helpers (unchanged core) ----------
__device__ __forceinline__ void load8(ull (&R)[8], const ull* rows, int rowidx, int base0){
  const ull* rp = rows + rowidx*PROW;
  #pragma unroll
  for (int mm=0; mm<2; mm++)
    #pragma unroll
    for (int k=0; k<4; k++) R[mm*4+k] = rp[base0 + 32*mm + k];
}
__device__ __forceinline__ void fma_ky(ull (&acc)[3][2][4],
                                       const ull (&T)[8], const ull (&Bt)[8],
                                       const float2* wb, int ci, int ky, int mh){
  #pragma unroll
  for (int co=0; co<3; co++){
    const ulonglong2* wp = (const ulonglong2*)(wb + (co*3+ci)*16 + ky*4);
    ulonglong2 w01 = wp[0], w23 = wp[1];
    #pragma unroll
    for (int mm=0; mm<2; mm++){
      const int m = 2*mh + mm;
      acc[co][0][m] = ffma2(T[mm*4+0],  w01.x, acc[co][0][m]);
      acc[co][0][m] = ffma2(T[mm*4+1],  w01.y, acc[co][0][m]);
      acc[co][0][m] = ffma2(T[mm*4+2],  w23.x, acc[co][0][m]);
      acc[co][0][m] = ffma2(T[mm*4+3],  w23.y, acc[co][0][m]);
      acc[co][1][m] = ffma2(Bt[mm*4+0], w01.x, acc[co][1][m]);
      acc[co][1][m] = ffma2(Bt[mm*4+1], w01.y, acc[co][1][m]);
      acc[co][1][m] = ffma2(Bt[mm*4+2], w23.x, acc[co][1][m]);
      acc[co][1][m] = ffma2(Bt[mm*4+3], w23.y, acc[co][1][m]);
    }
  }
}

// ---------- pass 2: persistent conv, TMA bulk plane fills ----------
extern __shared__ __align__(16) float2 dynslot[];

__global__ void __launch_bounds__(128, 4) conv_kernel(float* __restrict__ out){
  __shared__ __align__(16) float2 w_all[4*144];
  __shared__ __align__(8) ull mbars[NSLOT];
  __shared__ unsigned s_tile;

  const int tx  = threadIdx.x;
  const int ty  = threadIdx.y;
  const int tid = ty*32 + tx;
  const int r0  = 2*ty;

  const uint32_t slot_u32 = (uint32_t)__cvta_generic_to_shared(&dynslot[0]);
  const uint32_t mbar_u32 = (uint32_t)__cvta_generic_to_shared(&mbars[0]);

  if (tid < NSLOT) mbar_init(mbar_u32 + tid*8);
  unsigned ph = 0;                      // per-slot parity bits (uniform)

  int prev_v = -1, deg = 0;
  int src[4] = {0,0,0,0}, eid[4] = {0,0,0,0};
  float bsum[3] = {0.f,0.f,0.f};

  for (;;){
    if (tid == 0) s_tile = atomicAdd(&g_ctr, 1u);
    __syncthreads();                    // also covers mbar_init on first pass
    const unsigned t = s_tile;
    if (t >= NTILES) break;
    const int v   = (int)(t >> 7);
    const int rem = (int)(t & 127u);
    const int b   = rem >> 5;
    const int y0  = (rem & 31) * 8;
    if (v != prev_v){
      prev_v = v;
      deg = g_deg[v];
      #pragma unroll
      for (int i=0; i<4; i++){ src[i] = g_esr[v][i]; eid[i] = g_eid[v][i]; }
      bsum[0]=g_bsum[v][0]; bsum[1]=g_bsum[v][1]; bsum[2]=g_bsum[v][2];
      for (int q = tid; q < deg*144; q += 128)
        w_all[q] = g_wpk[eid[q/144]*144 + (q - (q/144)*144)];
      // visibility via the __syncthreads at s=0 below
    }

    // TMA fill of plane s_plane into slot s_plane&3.
    auto fill = [&](int s_plane){
      const int si = s_plane & 3;
      const int i  = s_plane/3;
      const int ci = s_plane - 3*i;
      const float2* pbase = g_pk + ((((size_t)src[i]*BB + b)*CC + ci)*HH)*(size_t)PROW;
      const uint32_t sb = slot_u32 + (uint32_t)(si*PLANE_BYTES);
      if (y0 == 0){
        if (tid == 0){
          mbar_expect_tx(mbar_u32 + si*8, 10*ROWB);
          tma_bulk(sb + ROWB, pbase, 10*ROWB, mbar_u32 + si*8);
        }
        if (tid < 66)
          asm volatile("st.shared.v4.b32 [%0], {%1,%1,%1,%1};"
                       :: "r"(sb + tid*16), "r"(0) : "memory");
      } else if (y0 == HH-8){
        if (tid == 0){
          mbar_expect_tx(mbar_u32 + si*8, 9*ROWB);
          tma_bulk(sb, pbase + (size_t)(y0-1)*PROW, 9*ROWB, mbar_u32 + si*8);
        }
        for (int z = tid; z < 132; z += 128)
          asm volatile("st.shared.v4.b32 [%0], {%1,%1,%1,%1};"
                       :: "r"(sb + 9*ROWB + z*16), "r"(0) : "memory");
      } else {
        if (tid == 0){
          mbar_expect_tx(mbar_u32 + si*8, 11*ROWB);
          tma_bulk(sb, pbase + (size_t)(y0-1)*PROW, 11*ROWB, mbar_u32 + si*8);
        }
      }
    };

    fill(0); fill(1); fill(2);

    ull acc[3][2][4];
    #pragma unroll
    for (int co=0; co<3; co++)
      #pragma unroll
      for (int rl=0; rl<2; rl++)
        #pragma unroll
        for (int m=0; m<4; m++) acc[co][rl][m] = 0ull;

    const int S = 3*deg;
    for (int s=0; s<S; s++){
      __syncthreads();                  // all warps done with plane s-1 -> slot free
      if (s+3 < S) fill(s+3);
      const int si = s & 3;
      mbar_wait(mbar_u32 + si*8, (ph >> si) & 1u);
      ph ^= (1u << si);

      const int i  = s/3;
      const int ci = s - 3*i;
      const ull* rows  = (const ull*)&dynslot[si*PLANE_F2];
      const float2* wb = w_all + i*144;

      #pragma unroll
      for (int mh=0; mh<2; mh++){
        const int base0 = tx + 64*mh;
        ull Ra[8], Rb[8];
        load8(Ra, rows, r0,   base0);
        load8(Rb, rows, r0+1, base0); fma_ky(acc, Ra, Rb, wb, ci, 0, mh);
        load8(Ra, rows, r0+2, base0); fma_ky(acc, Rb, Ra, wb, ci, 1, mh);
        load8(Rb, rows, r0+3, base0); fma_ky(acc, Ra, Rb, wb, ci, 2, mh);
        load8(Ra, rows, r0+4, base0); fma_ky(acc, Rb, Ra, wb, ci, 3, mh);
      }
    }

    const float inv = 1.f / (float)deg;
    #pragma unroll
    for (int co=0; co<3; co++){
      #pragma unroll
      for (int rl=0; rl<2; rl++){
        float* ob = out + (((size_t)v*BB + b)*CC + co)*HWSZ + (y0 + r0 + rl)*WW;
        #pragma unroll
        for (int m=0; m<4; m++){
          float lo, hi;
          upk2(acc[co][rl][m], lo, hi);
          int x = tx + 32*m;
          ob[x]       = (lo + bsum[co]) * inv;
          ob[x + 128] = (hi + bsum[co]) * inv;
        }
      }
    }
  }
}

extern "C" void kernel_launch(void* const* d_in, const int* in_sizes, int n_in,
                              void* d_out, int out_size){
  const float* states  = (const float*)d_in[0];
  const float* weights = (const float*)d_in[1];
  const float* bias    = (const float*)d_in[2];
  const int*   esrc    = (const int*)d_in[3];
  const int*   edst    = (const int*)d_in[4];
  float*       out     = (float*)d_out;

  const int nmain_blocks = (NROWS_TOTAL*32)/256;
  sigmoid_pack_all<<<nmain_blocks + 1, 256>>>(states, weights, bias, esrc, edst);

  static int smem_set = 0;
  if (!smem_set){
    cudaFuncSetAttribute(conv_kernel, cudaFuncAttributeMaxDynamicSharedMemorySize,
                         DYN_BYTES);
    smem_set = 1;
  }
  conv_kernel<<<NCTA, dim3(32,4), DYN_BYTES>>>(out);
}

// round 13
// speedup vs baseline: 1.2019x; 1.0870x over previous
#include <cuda_runtime.h>
#include <cstdint>

#define N_NODES 13
#define N_REAL  12
#define BB      4
#define CC      3
#define HH      256
#define WW      256
#define EE      37
#define HWSZ    (HH*WW)

// Packed activation row: 132 float2. idx 0 = {0, a[127]}, idx 1+j = {a[j], a[j+128]}
// (j=0..127), idx 129 = {a[128],0}, idx 130 = {a[129],0}, idx 131 = pad.
#define PROW 132
#define ROWB (PROW*8)                  // 1056 B per packed row
#define NROWS_TOTAL (N_NODES*BB*CC*HH)
#define TROWS 11
#define PLANE_F2 (TROWS*PROW)
#define PLANE_BYTES (PLANE_F2*8)       // 11616 B
#define NSLOT 4
#define DYN_BYTES (NSLOT*PLANE_BYTES)  // 46464 B
#define NTILES 1536
#define NCTA 592
typedef unsigned long long ull;

__device__ __align__(16) float2 g_pk[NROWS_TOTAL*PROW];
__device__ float2 g_wpk[EE*144];
__device__ int    g_deg[N_REAL];
__device__ int    g_esr[N_REAL][4];
__device__ int    g_eid[N_REAL][4];
__device__ float  g_bsum[N_REAL][3];
__device__ unsigned g_ctr;

__device__ __forceinline__ void upk2(ull v, float& lo, float& hi){
  asm("mov.b64 {%0, %1}, %2;" : "=f"(lo), "=f"(hi) : "l"(v));
}
__device__ __forceinline__ ull ffma2(ull a, ull b, ull c){
  ull d; asm("fma.rn.f32x2 %0, %1, %2, %3;" : "=l"(d) : "l"(a), "l"(b), "l"(c));
  return d;
}
__device__ __forceinline__ float sigf(float x){
  return __fdividef(1.f, 1.f + __expf(-x));
}
__device__ __forceinline__ void mbar_init(uint32_t bar){
  asm volatile("mbarrier.init.shared.b64 [%0], 1;" :: "r"(bar) : "memory");
}
__device__ __forceinline__ void mbar_expect_tx(uint32_t bar, uint32_t n){
  asm volatile("mbarrier.arrive.expect_tx.shared.b64 _, [%0], %1;"
               :: "r"(bar), "r"(n) : "memory");
}
__device__ __forceinline__ void tma_bulk(uint32_t dst, const void* src,
                                         uint32_t n, uint32_t bar){
  asm volatile("cp.async.bulk.shared::cta.global.mbarrier::complete_tx::bytes "
               "[%0], [%1], %2, [%3];"
               :: "r"(dst), "l"(src), "r"(n), "r"(bar) : "memory");
}
__device__ __forceinline__ void mbar_wait(uint32_t bar, uint32_t parity){
  asm volatile(
      "{\n\t.reg .pred P;\n\t"
      "WAIT_%=:\n\t"
      "mbarrier.try_wait.parity.acquire.cta.shared::cta.b64 P, [%0], %1, 0x989680;\n\t"
      "@P bra.uni DONE_%=;\n\t"
      "bra.uni WAIT_%=;\n\t"
      "DONE_%=:\n\t}"
      :: "r"(bar), "r"(parity) : "memory");
}

// ---------- pass 1: setup (block 0) + sigmoid pack + halo ----------
__global__ void sigmoid_pack_all(const float* __restrict__ x,
                                 const float* __restrict__ Wt,
                                 const float* __restrict__ Bs,
                                 const int*   __restrict__ esrc,
                                 const int*   __restrict__ edst){
  if (blockIdx.x == 0){
    int t = threadIdx.x;
    for (int i=t; i<EE*144; i+=256){ float w=__ldg(&Wt[i]); g_wpk[i]=make_float2(w,w); }
    if (t < N_REAL){
      int d=0; float b0=0.f,b1=0.f,b2=0.f;
      for (int e=0; e<EE; e++)
        if (__ldg(&edst[e]) == t){
          g_esr[t][d]=__ldg(&esrc[e]); g_eid[t][d]=e;
          b0+=__ldg(&Bs[e*3+0]); b1+=__ldg(&Bs[e*3+1]); b2+=__ldg(&Bs[e*3+2]);
          d++;
        }
      g_deg[t]=d; g_bsum[t][0]=b0; g_bsum[t][1]=b1; g_bsum[t][2]=b2;
    }
    if (t == 0) g_ctr = 0u;
    return;
  }
  int idx = (blockIdx.x-1)*256 + threadIdx.x;
  int rid = idx >> 5, q = idx & 31;
  const float4* in4 = (const float4*)(x + (size_t)rid*WW);
  float4 lo = __ldg(in4 + q);
  float4 hi = __ldg(in4 + q + 32);
  float slx=sigf(lo.x), sly=sigf(lo.y), slz=sigf(lo.z), slw=sigf(lo.w);
  float shx=sigf(hi.x), shy=sigf(hi.y), shz=sigf(hi.z), shw=sigf(hi.w);
  float2* row = g_pk + (size_t)rid*PROW;
  float2* o = row + 1 + 4*q;
  o[0] = make_float2(slx, shx);
  o[1] = make_float2(sly, shy);
  o[2] = make_float2(slz, shz);
  o[3] = make_float2(slw, shw);
  if (q == 31) row[0]   = make_float2(0.f, slw);
  if (q == 0){
    row[129] = make_float2(shx, 0.f);
    row[130] = make_float2(shy, 0.f);
    row[131] = make_float2(0.f, 0.f);
  }
}

// ---------- conv compute helpers ----------
// 5 taps covering out pair-cols {base, base+1}: idx base..base+4 (base even).
__device__ __forceinline__ void load5(ull (&R)[5], const ull* rows, int rowidx, int base){
  const ull* rp = rows + rowidx*PROW + base;
  ulonglong2 t0 = *(const ulonglong2*)(rp);      // LDS.128
  ulonglong2 t1 = *(const ulonglong2*)(rp + 2);  // LDS.128
  R[0]=t0.x; R[1]=t0.y; R[2]=t1.x; R[3]=t1.y;
  R[4]=rp[4];                                    // LDS.64
}
__device__ __forceinline__ void fma_ky(ull (&acc)[3][2][4],
                                       const ull (&T)[5], const ull (&Bt)[5],
                                       const float2* wb, int ci, int ky, int mh){
  #pragma unroll
  for (int co=0; co<3; co++){
    const ulonglong2* wp = (const ulonglong2*)(wb + (co*3+ci)*16 + ky*4);
    ulonglong2 w01 = wp[0], w23 = wp[1];         // broadcast LDS.128
    #pragma unroll
    for (int mm=0; mm<2; mm++){
      const int m = 2*mh + mm;
      acc[co][0][m] = ffma2(T[mm+0],  w01.x, acc[co][0][m]);
      acc[co][0][m] = ffma2(T[mm+1],  w01.y, acc[co][0][m]);
      acc[co][0][m] = ffma2(T[mm+2],  w23.x, acc[co][0][m]);
      acc[co][0][m] = ffma2(T[mm+3],  w23.y, acc[co][0][m]);
      acc[co][1][m] = ffma2(Bt[mm+0], w01.x, acc[co][1][m]);
      acc[co][1][m] = ffma2(Bt[mm+1], w01.y, acc[co][1][m]);
      acc[co][1][m] = ffma2(Bt[mm+2], w23.x, acc[co][1][m]);
      acc[co][1][m] = ffma2(Bt[mm+3], w23.y, acc[co][1][m]);
    }
  }
}

// ---------- pass 2: persistent conv, TMA plane fills ----------
extern __shared__ __align__(16) float2 dynslot[];

__global__ void __launch_bounds__(128, 4) conv_kernel(float* __restrict__ out){
  __shared__ __align__(16) float2 w_all[4*144];
  __shared__ __align__(8) ull mbars[NSLOT];
  __shared__ unsigned s_tile;

  const int tx  = threadIdx.x;
  const int ty  = threadIdx.y;
  const int tid = ty*32 + tx;
  const int r0  = 2*ty;

  const uint32_t slot_u32 = (uint32_t)__cvta_generic_to_shared(&dynslot[0]);
  const uint32_t mbar_u32 = (uint32_t)__cvta_generic_to_shared(&mbars[0]);

  if (tid < NSLOT) mbar_init(mbar_u32 + tid*8);
  unsigned ph = 0;

  int prev_v = -1, deg = 0;
  int src[4] = {0,0,0,0}, eid[4] = {0,0,0,0};
  float bsum[3] = {0.f,0.f,0.f};

  for (;;){
    if (tid == 0) s_tile = atomicAdd(&g_ctr, 1u);
    __syncthreads();
    const unsigned t = s_tile;
    if (t >= NTILES) break;
    const int v   = (int)(t >> 7);
    const int rem = (int)(t & 127u);
    const int b   = rem >> 5;
    const int y0  = (rem & 31) * 8;
    if (v != prev_v){
      prev_v = v;
      deg = g_deg[v];
      #pragma unroll
      for (int i=0; i<4; i++){ src[i] = g_esr[v][i]; eid[i] = g_eid[v][i]; }
      bsum[0]=g_bsum[v][0]; bsum[1]=g_bsum[v][1]; bsum[2]=g_bsum[v][2];
      for (int q = tid; q < deg*144; q += 128)
        w_all[q] = g_wpk[eid[q/144]*144 + (q - (q/144)*144)];
    }

    auto fill = [&](int s_plane){
      const int si = s_plane & 3;
      const int i  = s_plane/3;
      const int ci = s_plane - 3*i;
      const float2* pbase = g_pk + ((((size_t)src[i]*BB + b)*CC + ci)*HH)*(size_t)PROW;
      const uint32_t sb = slot_u32 + (uint32_t)(si*PLANE_BYTES);
      if (y0 == 0){
        if (tid == 0){
          mbar_expect_tx(mbar_u32 + si*8, 10*ROWB);
          tma_bulk(sb + ROWB, pbase, 10*ROWB, mbar_u32 + si*8);
        }
        if (tid < 66)
          asm volatile("st.shared.v4.b32 [%0], {%1,%1,%1,%1};"
                       :: "r"(sb + tid*16), "r"(0) : "memory");
      } else if (y0 == HH-8){
        if (tid == 0){
          mbar_expect_tx(mbar_u32 + si*8, 9*ROWB);
          tma_bulk(sb, pbase + (size_t)(y0-1)*PROW, 9*ROWB, mbar_u32 + si*8);
        }
        for (int z = tid; z < 132; z += 128)
          asm volatile("st.shared.v4.b32 [%0], {%1,%1,%1,%1};"
                       :: "r"(sb + 9*ROWB + z*16), "r"(0) : "memory");
      } else {
        if (tid == 0){
          mbar_expect_tx(mbar_u32 + si*8, 11*ROWB);
          tma_bulk(sb, pbase + (size_t)(y0-1)*PROW, 11*ROWB, mbar_u32 + si*8);
        }
      }
    };

    fill(0); fill(1); fill(2);

    ull acc[3][2][4];
    #pragma unroll
    for (int co=0; co<3; co++)
      #pragma unroll
      for (int rl=0; rl<2; rl++)
        #pragma unroll
        for (int m=0; m<4; m++) acc[co][rl][m] = 0ull;

    const int S = 3*deg;
    for (int s=0; s<S; s++){
      __syncthreads();                  // all warps done with slot being refilled
      if (s+3 < S) fill(s+3);
      const int si = s & 3;
      mbar_wait(mbar_u32 + si*8, (ph >> si) & 1u);
      ph ^= (1u << si);

      const int i  = s/3;
      const int ci = s - 3*i;
      const ull* rows  = (const ull*)&dynslot[si*PLANE_F2];
      const float2* wb = w_all + i*144;

      #pragma unroll
      for (int mh=0; mh<2; mh++){
        const int base = 2*tx + 64*mh;   // even -> 16B aligned taps
        ull Ra[5], Rb[5];
        load5(Ra, rows, r0,   base);
        load5(Rb, rows, r0+1, base); fma_ky(acc, Ra, Rb, wb, ci, 0, mh);
        load5(Ra, rows, r0+2, base); fma_ky(acc, Rb, Ra, wb, ci, 1, mh);
        load5(Rb, rows, r0+3, base); fma_ky(acc, Ra, Rb, wb, ci, 2, mh);
        load5(Ra, rows, r0+4, base); fma_ky(acc, Rb, Ra, wb, ci, 3, mh);
      }
    }

    // Epilogue: bias + mean; out cols per thread: {2tx,2tx+1,2tx+64,2tx+65} (+128 hi).
    const float inv = 1.f / (float)deg;
    #pragma unroll
    for (int co=0; co<3; co++){
      #pragma unroll
      for (int rl=0; rl<2; rl++){
        float* ob = out + (((size_t)v*BB + b)*CC + co)*HWSZ + (y0 + r0 + rl)*WW;
        #pragma unroll
        for (int mh=0; mh<2; mh++){
          float lo0, hi0, lo1, hi1;
          upk2(acc[co][rl][2*mh+0], lo0, hi0);
          upk2(acc[co][rl][2*mh+1], lo1, hi1);
          int x = 2*tx + 64*mh;
          *(float2*)(ob + x)       = make_float2((lo0+bsum[co])*inv, (lo1+bsum[co])*inv);
          *(float2*)(ob + x + 128) = make_float2((hi0+bsum[co])*inv, (hi1+bsum[co])*inv);
        }
      }
    }
  }
}

extern "C" void kernel_launch(void* const* d_in, const int* in_sizes, int n_in,
                              void* d_out, int out_size){
  const float* states  = (const float*)d_in[0];
  const float* weights = (const float*)d_in[1];
  const float* bias    = (const float*)d_in[2];
  const int*   esrc    = (const int*)d_in[3];
  const int*   edst    = (const int*)d_in[4];
  float*       out     = (float*)d_out;

  const int nmain_blocks = (NROWS_TOTAL*32)/256;
  sigmoid_pack_all<<<nmain_blocks + 1, 256>>>(states, weights, bias, esrc, edst);

  static int smem_set = 0;
  if (!smem_set){
    cudaFuncSetAttribute(conv_kernel, cudaFuncAttributeMaxDynamicSharedMemorySize,
                         DYN_BYTES);
    smem_set = 1;
  }
  conv_kernel<<<NCTA, dim3(32,4), DYN_BYTES>>>(out);
}

// round 14
// speedup vs baseline: 1.2093x; 1.0062x over previous
#include <cuda_runtime.h>
#include <cstdint>

#define N_NODES 13
#define N_REAL  12
#define BB      4
#define CC      3
#define HH      256
#define WW      256
#define EE      37
#define HWSZ    (HH*WW)

#define PROW 132
#define ROWB (PROW*8)                  // 1056 B per packed row
#define PSTR 259                       // padded rows per plane: 1 + 256 + 2
#define NPLANES (N_NODES*BB*CC)        // 156
#define TROWS 11
#define PLANE_F2 (TROWS*PROW)
#define PLANE_BYTES (PLANE_F2*8)       // 11616 B
#define NSLOT 4
#define DYN_BYTES (NSLOT*PLANE_BYTES)  // 46464 B
#define NTILES 1536
#define NCTA 592
typedef unsigned long long ull;

__device__ __align__(16) float2 g_pk[(size_t)NPLANES*PSTR*PROW];  // ~42.7 MB
__device__ float2 g_wpk[EE*144];
__device__ int    g_deg[N_REAL];
__device__ int    g_esr[N_REAL][4];
__device__ int    g_eid[N_REAL][4];
__device__ float  g_bsum[N_REAL][3];
__device__ unsigned g_ctr;

__device__ __forceinline__ void upk2(ull v, float& lo, float& hi){
  asm("mov.b64 {%0, %1}, %2;" : "=f"(lo), "=f"(hi) : "l"(v));
}
__device__ __forceinline__ ull ffma2(ull a, ull b, ull c){
  ull d; asm("fma.rn.f32x2 %0, %1, %2, %3;" : "=l"(d) : "l"(a), "l"(b), "l"(c));
  return d;
}
__device__ __forceinline__ float sigf(float x){
  return __fdividef(1.f, 1.f + __expf(-x));
}
__device__ __forceinline__ void mbar_init(uint32_t bar, uint32_t cnt){
  asm volatile("mbarrier.init.shared.b64 [%0], %1;" :: "r"(bar), "r"(cnt) : "memory");
}
__device__ __forceinline__ void mbar_expect_tx(uint32_t bar, uint32_t n){
  asm volatile("mbarrier.arrive.expect_tx.shared.b64 _, [%0], %1;"
               :: "r"(bar), "r"(n) : "memory");
}
__device__ __forceinline__ void mbar_arrive(uint32_t bar){
  asm volatile("mbarrier.arrive.shared.b64 _, [%0];" :: "r"(bar) : "memory");
}
__device__ __forceinline__ void tma_bulk(uint32_t dst, const void* src,
                                         uint32_t n, uint32_t bar){
  asm volatile("cp.async.bulk.shared::cta.global.mbarrier::complete_tx::bytes "
               "[%0], [%1], %2, [%3];"
               :: "r"(dst), "l"(src), "r"(n), "r"(bar) : "memory");
}
__device__ __forceinline__ void mbar_wait(uint32_t bar, uint32_t parity){
  asm volatile(
      "{\n\t.reg .pred P;\n\t"
      "WAIT_%=:\n\t"
      "mbarrier.try_wait.parity.acquire.cta.shared::cta.b64 P, [%0], %1, 0x989680;\n\t"
      "@P bra.uni DONE_%=;\n\t"
      "bra.uni WAIT_%=;\n\t"
      "DONE_%=:\n\t}"
      :: "r"(bar), "r"(parity) : "memory");
}

// ---------- pass 1: setup (blk 0) + sigmoid pack (blks 1..4992) + pads ----------
#define MAIN_BLKS ((N_NODES*BB*CC*HH*32)/256)        // 4992
#define PAD_F2   (NPLANES*3*PROW)                    // 61776
#define PAD_BLKS ((PAD_F2 + 255)/256)                // 242

__global__ void sigmoid_pack_all(const float* __restrict__ x,
                                 const float* __restrict__ Wt,
                                 const float* __restrict__ Bs,
                                 const int*   __restrict__ esrc,
                                 const int*   __restrict__ edst){
  if (blockIdx.x == 0){
    int t = threadIdx.x;
    for (int i=t; i<EE*144; i+=256){ float w=__ldg(&Wt[i]); g_wpk[i]=make_float2(w,w); }
    if (t < N_REAL){
      int d=0; float b0=0.f,b1=0.f,b2=0.f;
      for (int e=0; e<EE; e++)
        if (__ldg(&edst[e]) == t){
          g_esr[t][d]=__ldg(&esrc[e]); g_eid[t][d]=e;
          b0+=__ldg(&Bs[e*3+0]); b1+=__ldg(&Bs[e*3+1]); b2+=__ldg(&Bs[e*3+2]);
          d++;
        }
      g_deg[t]=d; g_bsum[t][0]=b0; g_bsum[t][1]=b1; g_bsum[t][2]=b2;
    }
    if (t == 0) g_ctr = 0u;
    return;
  }
  if (blockIdx.x <= MAIN_BLKS){
    int idx = (blockIdx.x-1)*256 + threadIdx.x;
    int rid = idx >> 5, q = idx & 31;                // rid = data row 0..39935
    const float4* in4 = (const float4*)(x + (size_t)rid*WW);
    float4 lo = __ldg(in4 + q);
    float4 hi = __ldg(in4 + q + 32);
    float slx=sigf(lo.x), sly=sigf(lo.y), slz=sigf(lo.z), slw=sigf(lo.w);
    float shx=sigf(hi.x), shy=sigf(hi.y), shz=sigf(hi.z), shw=sigf(hi.w);
    int plane = rid >> 8, r = rid & 255;
    float2* row = g_pk + ((size_t)plane*PSTR + 1 + r)*PROW;
    float2* o = row + 1 + 4*q;
    o[0] = make_float2(slx, shx);
    o[1] = make_float2(sly, shy);
    o[2] = make_float2(slz, shz);
    o[3] = make_float2(slw, shw);
    if (q == 31) row[0]   = make_float2(0.f, slw);
    if (q == 0){
      row[129] = make_float2(shx, 0.f);
      row[130] = make_float2(shy, 0.f);
      row[131] = make_float2(0.f, 0.f);
    }
    return;
  }
  // pad rows: per plane, padded rows 0, 257, 258 = zeros
  int z = (blockIdx.x - 1 - MAIN_BLKS)*256 + threadIdx.x;
  if (z >= PAD_F2) return;
  int plane = z / (3*PROW);
  int rem   = z - plane*(3*PROW);
  int which = rem / PROW;                            // 0,1,2
  int col   = rem - which*PROW;
  int prow  = (which == 0) ? 0 : (256 + which);      // 0, 257, 258
  g_pk[((size_t)plane*PSTR + prow)*PROW + col] = make_float2(0.f, 0.f);
}

// ---------- conv compute helpers ----------
__device__ __forceinline__ void load5(ull (&R)[5], const ull* rows, int rowidx, int base){
  const ull* rp = rows + rowidx*PROW + base;
  ulonglong2 t0 = *(const ulonglong2*)(rp);
  ulonglong2 t1 = *(const ulonglong2*)(rp + 2);
  R[0]=t0.x; R[1]=t0.y; R[2]=t1.x; R[3]=t1.y;
  R[4]=rp[4];
}
__device__ __forceinline__ void fma_ky(ull (&acc)[3][2][4],
                                       const ull (&T)[5], const ull (&Bt)[5],
                                       const float2* wb, int ci, int ky, int mh){
  #pragma unroll
  for (int co=0; co<3; co++){
    const ulonglong2* wp = (const ulonglong2*)(wb + (co*3+ci)*16 + ky*4);
    ulonglong2 w01 = wp[0], w23 = wp[1];
    #pragma unroll
    for (int mm=0; mm<2; mm++){
      const int m = 2*mh + mm;
      acc[co][0][m] = ffma2(T[mm+0],  w01.x, acc[co][0][m]);
      acc[co][0][m] = ffma2(T[mm+1],  w01.y, acc[co][0][m]);
      acc[co][0][m] = ffma2(T[mm+2],  w23.x, acc[co][0][m]);
      acc[co][0][m] = ffma2(T[mm+3],  w23.y, acc[co][0][m]);
      acc[co][1][m] = ffma2(Bt[mm+0], w01.x, acc[co][1][m]);
      acc[co][1][m] = ffma2(Bt[mm+1], w01.y, acc[co][1][m]);
      acc[co][1][m] = ffma2(Bt[mm+2], w23.x, acc[co][1][m]);
      acc[co][1][m] = ffma2(Bt[mm+3], w23.y, acc[co][1][m]);
    }
  }
}

// ---------- pass 2: persistent conv, producer/consumer mbarrier pipeline ----------
extern __shared__ __align__(16) float2 dynslot[];

__global__ void __launch_bounds__(128, 4) conv_kernel(float* __restrict__ out){
  __shared__ __align__(16) float2 w_all[4*144];
  __shared__ __align__(8) ull mbars[2*NSLOT];        // [0..3]=full, [4..7]=empty
  __shared__ unsigned s_tile;

  const int tx  = threadIdx.x;
  const int ty  = threadIdx.y;
  const int tid = ty*32 + tx;
  const int r0  = 2*ty;

  const uint32_t slot_u32 = (uint32_t)__cvta_generic_to_shared(&dynslot[0]);
  const uint32_t mbar_u32 = (uint32_t)__cvta_generic_to_shared(&mbars[0]);
  #define FULLB(si)  (mbar_u32 + (si)*8u)
  #define EMPTYB(si) (mbar_u32 + 32u + (si)*8u)

  if (tid < NSLOT)      mbar_init(FULLB(tid), 1);
  else if (tid < 2*NSLOT) mbar_init(EMPTYB(tid-NSLOT), 4);

  unsigned ph = 0, eph = 0;            // per-slot parity: full (consumer), empty (producer)
  unsigned P  = 0;                     // global plane counter (uniform)

  int prev_v = -1, deg = 0;
  int src[4] = {0,0,0,0}, eid[4] = {0,0,0,0};
  float bsum[3] = {0.f,0.f,0.f};

  for (;;){
    if (tid == 0) s_tile = atomicAdd(&g_ctr, 1u);
    __syncthreads();                   // publish s_tile; covers mbar_init on 1st pass
    const unsigned t = s_tile;
    if (t >= NTILES) break;
    const int v   = (int)(t >> 7);
    const int rem = (int)(t & 127u);
    const int b   = rem >> 5;
    const int y0  = (rem & 31) * 8;
    if (v != prev_v){
      prev_v = v;
      deg = g_deg[v];
      #pragma unroll
      for (int i=0; i<4; i++){ src[i] = g_esr[v][i]; eid[i] = g_eid[v][i]; }
      bsum[0]=g_bsum[v][0]; bsum[1]=g_bsum[v][1]; bsum[2]=g_bsum[v][2];
      for (int q = tid; q < deg*144; q += 128)
        w_all[q] = g_wpk[eid[q/144]*144 + (q - (q/144)*144)];
      __syncthreads();                 // w_all visible before compute
    }
    const int S = 3*deg;

    // Producer: fill plane with local index sl (global id g = P + sl).
    auto produce = [&](int sl){
      const unsigned g = P + (unsigned)sl;
      const int si = (int)(g & 3u);
      if (g >= 4u){                    // wait slot free (4 warp-arrives from g-4)
        mbar_wait(EMPTYB(si), (eph >> si) & 1u);
        eph ^= (1u << si);
      }
      const int i = sl/3, ci = sl - 3*i;
      const int pl = (src[i]*BB + b)*CC + ci;
      const char* sp = (const char*)g_pk + ((size_t)pl*PSTR + y0)*ROWB;
      mbar_expect_tx(FULLB(si), 11*ROWB);
      tma_bulk(slot_u32 + (uint32_t)(si*PLANE_BYTES), sp, 11*ROWB, FULLB(si));
    };

    if (tid == 0){ produce(0); produce(1); produce(2); }

    ull acc[3][2][4];
    #pragma unroll
    for (int co=0; co<3; co++)
      #pragma unroll
      for (int rl=0; rl<2; rl++)
        #pragma unroll
        for (int m=0; m<4; m++) acc[co][rl][m] = 0ull;

    for (int s=0; s<S; s++){
      if (tid == 0 && s+3 < S) produce(s+3);
      const int si = (int)((P + (unsigned)s) & 3u);
      mbar_wait(FULLB(si), (ph >> si) & 1u);
      ph ^= (1u << si);

      const int i  = s/3;
      const int ci = s - 3*i;
      const ull* rows  = (const ull*)&dynslot[si*PLANE_F2];
      const float2* wb = w_all + i*144;

      #pragma unroll
      for (int mh=0; mh<2; mh++){
        const int base = 2*tx + 64*mh;
        ull Ra[5], Rb[5];
        load5(Ra, rows, r0,   base);
        load5(Rb, rows, r0+1, base); fma_ky(acc, Ra, Rb, wb, ci, 0, mh);
        load5(Ra, rows, r0+2, base); fma_ky(acc, Rb, Ra, wb, ci, 1, mh);
        load5(Rb, rows, r0+3, base); fma_ky(acc, Ra, Rb, wb, ci, 2, mh);
        load5(Ra, rows, r0+4, base); fma_ky(acc, Rb, Ra, wb, ci, 3, mh);
      }
      __syncwarp();                    // all lanes' reads happen-before the arrive
      if (tx == 0) mbar_arrive(EMPTYB(si));
    }
    P += (unsigned)S;

    const float inv = 1.f / (float)deg;
    #pragma unroll
    for (int co=0; co<3; co++){
      #pragma unroll
      for (int rl=0; rl<2; rl++){
        float* ob = out + (((size_t)v*BB + b)*CC + co)*HWSZ + (y0 + r0 + rl)*WW;
        #pragma unroll
        for (int mh=0; mh<2; mh++){
          float lo0, hi0, lo1, hi1;
          upk2(acc[co][rl][2*mh+0], lo0, hi0);
          upk2(acc[co][rl][2*mh+1], lo1, hi1);
          int x = 2*tx + 64*mh;
          *(float2*)(ob + x)       = make_float2((lo0+bsum[co])*inv, (lo1+bsum[co])*inv);
          *(float2*)(ob + x + 128) = make_float2((hi0+bsum[co])*inv, (hi1+bsum[co])*inv);
        }
      }
    }
  }
}

extern "C" void kernel_launch(void* const* d_in, const int* in_sizes, int n_in,
                              void* d_out, int out_size){
  const float* states  = (const float*)d_in[0];
  const float* weights = (const float*)d_in[1];
  const float* bias    = (const float*)d_in[2];
  const int*   esrc    = (const int*)d_in[3];
  const int*   edst    = (const int*)d_in[4];
  float*       out     = (float*)d_out;

  sigmoid_pack_all<<<1 + MAIN_BLKS + PAD_BLKS, 256>>>(states, weights, bias, esrc, edst);

  static int smem_set = 0;
  if (!smem_set){
    cudaFuncSetAttribute(conv_kernel, cudaFuncAttributeMaxDynamicSharedMemorySize,
                         DYN_BYTES);
    smem_set = 1;
  }
  conv_kernel<<<NCTA, dim3(32,4), DYN_BYTES>>>(out);
}